// round 12
// baseline (speedup 1.0000x reference)
#include <cuda_runtime.h>
#include <math.h>
#include <stdint.h>

#define NB   2
#define SEQ  2048
#define EMB  1024
#define NH   16
#define NKV  8
#define HD   64
#define MROWS (NB*SEQ)   // 4096

// ---------------- scratch (no allocations allowed) ----------------
__device__ float g_q[(size_t)MROWS * NH * HD];    // QSC-scaled, tf32, d-permuted
__device__ float g_k[(size_t)MROWS * NKV * HD];   // tf32, d-permuted
__device__ float g_v[(size_t)MROWS * NKV * HD];   // tf32
__device__ float g_attn[(size_t)MROWS * NH * HD]; // tf32 (flash epilogue)
__device__ float g_xt[(size_t)MROWS * EMB];       // tf32 x
__device__ float g_wq[(size_t)NH * HD * EMB];     // tf32, rows d-permuted
__device__ float g_wk[(size_t)NKV * HD * EMB];    // tf32, rows d-permuted
__device__ float g_wv[(size_t)NKV * HD * EMB];
__device__ float g_wo[(size_t)EMB * NH * HD];

#define QSC 0.18033688011112042f   // 0.125 * log2(e)

// =====================================================================
// helpers
// =====================================================================
__device__ __forceinline__ uint32_t f2tf(float f) {
    uint32_t u;
    asm("cvt.rna.tf32.f32 %0, %1;" : "=r"(u) : "f"(f));
    return u;
}
__device__ __forceinline__ void mma_tf32(float* d, const uint32_t* a, const uint32_t* b) {
    asm volatile(
        "mma.sync.aligned.m16n8k8.row.col.f32.tf32.tf32.f32 "
        "{%0,%1,%2,%3}, {%4,%5,%6,%7}, {%8,%9}, {%0,%1,%2,%3};"
        : "+f"(d[0]), "+f"(d[1]), "+f"(d[2]), "+f"(d[3])
        : "r"(a[0]), "r"(a[1]), "r"(a[2]), "r"(a[3]), "r"(b[0]), "r"(b[1]));
}
__device__ __forceinline__ uint32_t smem_u32(const void* p) {
    uint32_t a;
    asm("{ .reg .u64 t; cvta.to.shared.u64 t, %1; cvt.u32.u64 %0, t; }" : "=r"(a) : "l"(p));
    return a;
}
#define CPCA16(dst, src) \
    asm volatile("cp.async.ca.shared.global [%0], [%1], 16;" :: "r"(dst), "l"(src))
#define CP_COMMIT() asm volatile("cp.async.commit_group;" ::: "memory")
#define CP_WAIT(n)  asm volatile("cp.async.wait_group %0;" :: "n"(n) : "memory")

// sigma: within each 8-group, d -> 2*(d&3) + ((d>>2)&1)
__device__ __forceinline__ int dperm(int r) {
    return (r & ~7) | (((r & 3) << 1) | ((r >> 2) & 1));
}

// =====================================================================
// pre-round: x + weights -> tf32 scratch; Wq/Wk rows d-permuted
// =====================================================================
#define X4  (MROWS * EMB / 4)
#define WQ4 (NH * HD * EMB / 4)
#define WK4 (NKV * HD * EMB / 4)
#define TOT4 (X4 + WQ4 + 2 * WK4 + WQ4)

__global__ __launch_bounds__(256)
void preround(const float* __restrict__ x,
              const float* __restrict__ wq, const float* __restrict__ wk,
              const float* __restrict__ wv, const float* __restrict__ wo)
{
    long i = (long)blockIdx.x * 256 + threadIdx.x;
    const float* src; float* dst; long base; int permute = 0;
    if (i < X4)                       { src = x;  dst = g_xt; base = 0; }
    else if (i < X4 + WQ4)            { src = wq; dst = g_wq; base = X4; permute = 1; }
    else if (i < X4 + WQ4 + WK4)      { src = wk; dst = g_wk; base = X4 + WQ4; permute = 1; }
    else if (i < X4 + WQ4 + 2 * WK4)  { src = wv; dst = g_wv; base = X4 + WQ4 + WK4; }
    else                              { src = wo; dst = g_wo; base = X4 + WQ4 + 2 * WK4; }
    long j = (i - base) * 4;
    float4 a = *(const float4*)(src + j);
    uint4 t = { f2tf(a.x), f2tf(a.y), f2tf(a.z), f2tf(a.w) };
    long dj = j;
    if (permute) {
        int row = (int)(j >> 10);          // EMB = 1024
        int col = (int)(j & 1023);
        dj = ((long)dperm(row) << 10) + col;
    }
    *(uint4*)(dst + dj) = t;
}

// =====================================================================
// mma.sync tf32 GEMM v4 (unchanged from R11): 256 thr, 8 warps (2x4),
// warp tile 64x64, CTA 128x256, K-chunk 32, cp.async.ca double-buffered.
// =====================================================================
#define LT 36
#define ABUF (128 * LT)
#define BBUF (256 * LT)
#define TBUF (ABUF + BBUF)
#define GSMEM_DYN (2 * TBUF * 4)

__device__ __forceinline__
void gemm_stage(uint32_t sbase, int buf, const float* __restrict__ A,
                const float* __restrict__ B, int K, int m0, int n0, int k0, int tid)
{
    uint32_t dA = sbase + (buf * TBUF) * 4;
    uint32_t dB = dA + ABUF * 4;
#pragma unroll
    for (int p = 0; p < 4; p++) {
        int c = tid + p * 256;
        int row = c >> 3;
        int c4  = (c & 7) * 4;
        CPCA16(dA + (row * LT + c4) * 4, A + (size_t)(m0 + row) * K + k0 + c4);
    }
#pragma unroll
    for (int p = 0; p < 8; p++) {
        int c = tid + p * 256;
        int row = c >> 3;
        int c4  = (c & 7) * 4;
        CPCA16(dB + (row * LT + c4) * 4, B + (size_t)(n0 + row) * K + k0 + c4);
    }
    CP_COMMIT();
}

__device__ __forceinline__
void gemm_body(const float* __restrict__ A, const float* __restrict__ B,
               const float* __restrict__ bias, float* __restrict__ C,
               int N, int K, int m0, int n0, int mode)
{
    extern __shared__ uint32_t gsm[];
    const uint32_t sbase = smem_u32(gsm);

    const int tid  = threadIdx.x;
    const int lane = tid & 31;
    const int wid  = tid >> 5;
    const int wm   = wid >> 2;
    const int wn   = wid & 3;
    const int fr   = lane >> 2;
    const int fc   = lane & 3;

    float acc[4][8][4];
#pragma unroll
    for (int mt = 0; mt < 4; mt++)
#pragma unroll
        for (int nt = 0; nt < 8; nt++)
#pragma unroll
            for (int i = 0; i < 4; i++) acc[mt][nt][i] = 0.f;

    gemm_stage(sbase, 0, A, B, K, m0, n0, 0, tid);

    const int NC = K / 32;
    for (int ch = 0; ch < NC; ch++) {
        if (ch + 1 < NC) {
            gemm_stage(sbase, (ch + 1) & 1, A, B, K, m0, n0, (ch + 1) * 32, tid);
            CP_WAIT(1);
        } else {
            CP_WAIT(0);
        }
        __syncthreads();

        const uint32_t* As = gsm + (ch & 1) * TBUF;
        const uint32_t* Bs = As + ABUF;

#pragma unroll
        for (int ks = 0; ks < 4; ks++) {
            uint32_t af[4][4], bf[8][2];
#pragma unroll
            for (int mt = 0; mt < 4; mt++) {
                int m = wm * 64 + mt * 16 + fr;
                af[mt][0] = As[m * LT + ks * 8 + fc];
                af[mt][1] = As[(m + 8) * LT + ks * 8 + fc];
                af[mt][2] = As[m * LT + ks * 8 + fc + 4];
                af[mt][3] = As[(m + 8) * LT + ks * 8 + fc + 4];
            }
#pragma unroll
            for (int nt = 0; nt < 8; nt++) {
                int n = wn * 64 + nt * 8 + fr;
                bf[nt][0] = Bs[n * LT + ks * 8 + fc];
                bf[nt][1] = Bs[n * LT + ks * 8 + fc + 4];
            }
#pragma unroll
            for (int mt = 0; mt < 4; mt++)
#pragma unroll
                for (int nt = 0; nt < 8; nt++)
                    mma_tf32(acc[mt][nt], af[mt], bf[nt]);
        }
        __syncthreads();
    }

    const int c2 = (lane & 3) * 2;
#pragma unroll
    for (int mt = 0; mt < 4; mt++) {
        int m = m0 + wm * 64 + mt * 16 + fr;
#pragma unroll
        for (int nt = 0; nt < 8; nt++) {
            int n = n0 + wn * 64 + nt * 8 + c2;
            float2 v0, v1;
            if (mode == 0) {
                float b0 = bias ? bias[n] : 0.f, b1 = bias ? bias[n + 1] : 0.f;
                v0 = make_float2(acc[mt][nt][0] + b0, acc[mt][nt][1] + b1);
                v1 = make_float2(acc[mt][nt][2] + b0, acc[mt][nt][3] + b1);
            } else {
                float sc = (mode == 2) ? QSC : 1.f;
                v0.x = __uint_as_float(f2tf(acc[mt][nt][0] * sc));
                v0.y = __uint_as_float(f2tf(acc[mt][nt][1] * sc));
                v1.x = __uint_as_float(f2tf(acc[mt][nt][2] * sc));
                v1.y = __uint_as_float(f2tf(acc[mt][nt][3] * sc));
            }
            *(float2*)(C + (size_t)m * N + n)       = v0;
            *(float2*)(C + (size_t)(m + 8) * N + n) = v1;
        }
    }
}

// fused QKV: blockIdx.x 0..3 -> Q, 4..5 -> K, 6..7 -> V
__global__ __launch_bounds__(256)
void gemm_qkv(float* __restrict__ q, float* __restrict__ k, float* __restrict__ v)
{
    const int bx = blockIdx.x;
    const int m0 = blockIdx.y * 128;
    if (bx < 4)      gemm_body(g_xt, g_wq, nullptr, q, NH * HD,  EMB, m0, bx * 256, 2);
    else if (bx < 6) gemm_body(g_xt, g_wk, nullptr, k, NKV * HD, EMB, m0, (bx - 4) * 256, 1);
    else             gemm_body(g_xt, g_wv, nullptr, v, NKV * HD, EMB, m0, (bx - 6) * 256, 1);
}

__global__ __launch_bounds__(256)
void gemm_out(const float* __restrict__ bias, float* __restrict__ C)
{
    gemm_body(g_attn, g_wo, bias, C, EMB, EMB, blockIdx.y * 128, blockIdx.x * 256, 0);
}

// =====================================================================
// Flash attention (mma.sync tf32), v7:
// BK=128 staging (half the barriers), d-permuted Q/K -> K/Q fragment
// loads are LDS.64 (Kt stride 72, bank 8fr+2fc conflict-free).
// 4 warps x 32 q-rows (BQ=128).
// Ks/Vs: [128][72].  Ps: [128][68].
// =====================================================================
#define LTK 72
#define LTV 72
#define LTT 68

__global__ __launch_bounds__(128, 2)
void flash_mma()
{
    extern __shared__ uint32_t smf[];
    uint32_t* Ks = smf;                   // [128][72]
    uint32_t* Vs = Ks + 128 * LTK;        // [128][72]
    uint32_t* Ps = Vs + 128 * LTV;        // [128][68]

    const int tid  = threadIdx.x;
    const int lane = tid & 31;
    const int wid  = tid >> 5;
    const int fr   = lane >> 2;
    const int fc   = lane & 3;

    const int q0 = blockIdx.x * 128;
    const int h  = blockIdx.y;
    const int n  = blockIdx.z;
    const int kvh = h >> 1;
    const float slope2 = exp2f(-(float)(h + 1)) * QSC;

    // ---- stage Q (pre-scaled/rounded/permuted): plain copy ----
#pragma unroll
    for (int p = 0; p < 16; p++) {
        int f4 = tid + p * 128;
        int qi = f4 >> 4;
        int d4 = f4 & 15;
        uint4 t = *(const uint4*)(g_q + (size_t)(n * SEQ + q0 + qi) * (NH * HD)
                                      + h * HD + d4 * 4);
        *(uint4*)&Ps[qi * LTT + d4 * 4] = t;
    }
    __syncthreads();

    const int r0 = wid * 32 + fr;
    uint32_t qf0[8][4], qf1[8][4];
#pragma unroll
    for (int ks = 0; ks < 8; ks++) {
        // permuted: physical (ks*8+2fc, +1) = logical (fc, fc+4) = (a0,a2)/(a1,a3)
        uint2 qa = *(const uint2*)&Ps[r0 * LTT + ks * 8 + 2 * fc];
        uint2 qb = *(const uint2*)&Ps[(r0 + 8) * LTT + ks * 8 + 2 * fc];
        qf0[ks][0] = qa.x; qf0[ks][2] = qa.y;
        qf0[ks][1] = qb.x; qf0[ks][3] = qb.y;
        uint2 qc = *(const uint2*)&Ps[(r0 + 16) * LTT + ks * 8 + 2 * fc];
        uint2 qd = *(const uint2*)&Ps[(r0 + 24) * LTT + ks * 8 + 2 * fc];
        qf1[ks][0] = qc.x; qf1[ks][2] = qc.y;
        qf1[ks][1] = qd.x; qf1[ks][3] = qd.y;
    }

    float o0[8][4], o1[8][4];
#pragma unroll
    for (int nt = 0; nt < 8; nt++)
#pragma unroll
        for (int i = 0; i < 4; i++) { o0[nt][i] = 0.f; o1[nt][i] = 0.f; }
    float m00 = -INFINITY, m01 = -INFINITY, m10 = -INFINITY, m11 = -INFINITY;
    float l00 = 0.f, l01 = 0.f, l10 = 0.f, l11 = 0.f;

    const float gq0 = (float)(q0 + wid * 32 + fr);

    for (int kb = 0; kb < SEQ / 128; kb++) {
        __syncthreads();   // WAR: all warps done with previous Ks/Vs

        // ---- stage 128 keys of K and V ----
#pragma unroll
        for (int p = 0; p < 16; p++) {
            int f4 = tid + p * 128;
            int ki = f4 >> 4;            // 0..127
            int d4 = f4 & 15;
            size_t gk = (size_t)(n * SEQ + kb * 128 + ki) * (NKV * HD) + kvh * HD + d4 * 4;
            uint4 ta = *(const uint4*)(g_k + gk);
            *(uint4*)&Ks[ki * LTK + d4 * 4] = ta;
            uint4 tb = *(const uint4*)(g_v + gk);
            *(uint4*)&Vs[ki * LTV + d4 * 4] = tb;
        }
        __syncthreads();

        // ---- two 64-key compute passes on the staged tile ----
#pragma unroll
        for (int kk = 0; kk < 2; kk++) {
            const uint32_t* K_ = Ks + kk * 64 * LTK;
            const uint32_t* V_ = Vs + kk * 64 * LTV;

            // ---- S = Q @ K^T (K frags via LDS.64, permuted) ----
            float s0[8][4], s1[8][4];
#pragma unroll
            for (int nt = 0; nt < 8; nt++)
#pragma unroll
                for (int i = 0; i < 4; i++) { s0[nt][i] = 0.f; s1[nt][i] = 0.f; }

#pragma unroll
            for (int ks = 0; ks < 8; ks++) {
                uint2 bfp[8];
#pragma unroll
                for (int nt = 0; nt < 8; nt++)
                    bfp[nt] = *(const uint2*)&K_[(nt * 8 + fr) * LTK + ks * 8 + 2 * fc];
#pragma unroll
                for (int nt = 0; nt < 8; nt++) {
                    uint32_t bf[2] = { bfp[nt].x, bfp[nt].y };
                    mma_tf32(s0[nt], qf0[ks], bf);
                    mma_tf32(s1[nt], qf1[ks], bf);
                }
            }

            // ---- ALiBi (exp2 domain) ----
#pragma unroll
            for (int nt = 0; nt < 8; nt++) {
                float k0f = (float)(kb * 128 + kk * 64 + nt * 8 + 2 * fc);
                float k1f = k0f + 1.f;
                s0[nt][0] = fmaf(-slope2, fabsf(gq0 - k0f), s0[nt][0]);
                s0[nt][1] = fmaf(-slope2, fabsf(gq0 - k1f), s0[nt][1]);
                s0[nt][2] = fmaf(-slope2, fabsf((gq0 + 8.f) - k0f), s0[nt][2]);
                s0[nt][3] = fmaf(-slope2, fabsf((gq0 + 8.f) - k1f), s0[nt][3]);
                s1[nt][0] = fmaf(-slope2, fabsf((gq0 + 16.f) - k0f), s1[nt][0]);
                s1[nt][1] = fmaf(-slope2, fabsf((gq0 + 16.f) - k1f), s1[nt][1]);
                s1[nt][2] = fmaf(-slope2, fabsf((gq0 + 24.f) - k0f), s1[nt][2]);
                s1[nt][3] = fmaf(-slope2, fabsf((gq0 + 24.f) - k1f), s1[nt][3]);
            }

            // ---- online softmax, block0 ----
            {
                float mt0 = -INFINITY, mt1 = -INFINITY;
#pragma unroll
                for (int nt = 0; nt < 8; nt++) {
                    mt0 = fmaxf(mt0, fmaxf(s0[nt][0], s0[nt][1]));
                    mt1 = fmaxf(mt1, fmaxf(s0[nt][2], s0[nt][3]));
                }
                mt0 = fmaxf(mt0, __shfl_xor_sync(0xffffffffu, mt0, 1));
                mt0 = fmaxf(mt0, __shfl_xor_sync(0xffffffffu, mt0, 2));
                mt1 = fmaxf(mt1, __shfl_xor_sync(0xffffffffu, mt1, 1));
                mt1 = fmaxf(mt1, __shfl_xor_sync(0xffffffffu, mt1, 2));
                float mn0 = fmaxf(m00, mt0), mn1 = fmaxf(m01, mt1);
                float c0 = exp2f(m00 - mn0), c1 = exp2f(m01 - mn1);
                m00 = mn0; m01 = mn1;
                float rs0 = 0.f, rs1 = 0.f;
#pragma unroll
                for (int nt = 0; nt < 8; nt++) {
                    float p0 = exp2f(s0[nt][0] - mn0);
                    float p1 = exp2f(s0[nt][1] - mn0);
                    float p2 = exp2f(s0[nt][2] - mn1);
                    float p3 = exp2f(s0[nt][3] - mn1);
                    rs0 += p0 + p1; rs1 += p2 + p3;
                    uint2 w0 = { f2tf(p0), f2tf(p1) };
                    uint2 w1 = { f2tf(p2), f2tf(p3) };
                    *(uint2*)&Ps[r0 * LTT + nt * 8 + 2 * fc]       = w0;
                    *(uint2*)&Ps[(r0 + 8) * LTT + nt * 8 + 2 * fc] = w1;
                }
                rs0 += __shfl_xor_sync(0xffffffffu, rs0, 1);
                rs0 += __shfl_xor_sync(0xffffffffu, rs0, 2);
                rs1 += __shfl_xor_sync(0xffffffffu, rs1, 1);
                rs1 += __shfl_xor_sync(0xffffffffu, rs1, 2);
                l00 = l00 * c0 + rs0;
                l01 = l01 * c1 + rs1;
#pragma unroll
                for (int nt = 0; nt < 8; nt++) {
                    o0[nt][0] *= c0; o0[nt][1] *= c0;
                    o0[nt][2] *= c1; o0[nt][3] *= c1;
                }
            }
            // ---- online softmax, block1 ----
            {
                float mt0 = -INFINITY, mt1 = -INFINITY;
#pragma unroll
                for (int nt = 0; nt < 8; nt++) {
                    mt0 = fmaxf(mt0, fmaxf(s1[nt][0], s1[nt][1]));
                    mt1 = fmaxf(mt1, fmaxf(s1[nt][2], s1[nt][3]));
                }
                mt0 = fmaxf(mt0, __shfl_xor_sync(0xffffffffu, mt0, 1));
                mt0 = fmaxf(mt0, __shfl_xor_sync(0xffffffffu, mt0, 2));
                mt1 = fmaxf(mt1, __shfl_xor_sync(0xffffffffu, mt1, 1));
                mt1 = fmaxf(mt1, __shfl_xor_sync(0xffffffffu, mt1, 2));
                float mn0 = fmaxf(m10, mt0), mn1 = fmaxf(m11, mt1);
                float c0 = exp2f(m10 - mn0), c1 = exp2f(m11 - mn1);
                m10 = mn0; m11 = mn1;
                float rs0 = 0.f, rs1 = 0.f;
#pragma unroll
                for (int nt = 0; nt < 8; nt++) {
                    float p0 = exp2f(s1[nt][0] - mn0);
                    float p1 = exp2f(s1[nt][1] - mn0);
                    float p2 = exp2f(s1[nt][2] - mn1);
                    float p3 = exp2f(s1[nt][3] - mn1);
                    rs0 += p0 + p1; rs1 += p2 + p3;
                    uint2 w0 = { f2tf(p0), f2tf(p1) };
                    uint2 w1 = { f2tf(p2), f2tf(p3) };
                    *(uint2*)&Ps[(r0 + 16) * LTT + nt * 8 + 2 * fc] = w0;
                    *(uint2*)&Ps[(r0 + 24) * LTT + nt * 8 + 2 * fc] = w1;
                }
                rs0 += __shfl_xor_sync(0xffffffffu, rs0, 1);
                rs0 += __shfl_xor_sync(0xffffffffu, rs0, 2);
                rs1 += __shfl_xor_sync(0xffffffffu, rs1, 1);
                rs1 += __shfl_xor_sync(0xffffffffu, rs1, 2);
                l10 = l10 * c0 + rs0;
                l11 = l11 * c1 + rs1;
#pragma unroll
                for (int nt = 0; nt < 8; nt++) {
                    o1[nt][0] *= c0; o1[nt][1] *= c0;
                    o1[nt][2] *= c1; o1[nt][3] *= c1;
                }
            }
            __syncwarp();

            // ---- O += P @ V ----
#pragma unroll
            for (int ks = 0; ks < 8; ks++) {
                uint32_t af0[4], af1[4], bf[8][2];
                af0[0] = Ps[r0 * LTT + ks * 8 + fc];
                af0[1] = Ps[(r0 + 8) * LTT + ks * 8 + fc];
                af0[2] = Ps[r0 * LTT + ks * 8 + fc + 4];
                af0[3] = Ps[(r0 + 8) * LTT + ks * 8 + fc + 4];
                af1[0] = Ps[(r0 + 16) * LTT + ks * 8 + fc];
                af1[1] = Ps[(r0 + 24) * LTT + ks * 8 + fc];
                af1[2] = Ps[(r0 + 16) * LTT + ks * 8 + fc + 4];
                af1[3] = Ps[(r0 + 24) * LTT + ks * 8 + fc + 4];
#pragma unroll
                for (int nt = 0; nt < 8; nt++) {
                    bf[nt][0] = V_[(ks * 8 + fc) * LTV + nt * 8 + fr];
                    bf[nt][1] = V_[(ks * 8 + fc + 4) * LTV + nt * 8 + fr];
                }
#pragma unroll
                for (int nt = 0; nt < 8; nt++) {
                    mma_tf32(o0[nt], af0, bf[nt]);
                    mma_tf32(o1[nt], af1, bf[nt]);
                }
            }
            __syncwarp();   // P (Ps) reuse safety between the two passes
        }
    }

    // ---- normalize + write (tf32-rounded) ----
    {
        float i00 = 1.f / l00, i01 = 1.f / l01, i10 = 1.f / l10, i11 = 1.f / l11;
        const int qr = q0 + wid * 32 + fr;
        float* b0 = g_attn + (size_t)(n * SEQ + qr) * (NH * HD) + h * HD;
        float* b1 = g_attn + (size_t)(n * SEQ + qr + 8) * (NH * HD) + h * HD;
        float* b2 = g_attn + (size_t)(n * SEQ + qr + 16) * (NH * HD) + h * HD;
        float* b3 = g_attn + (size_t)(n * SEQ + qr + 24) * (NH * HD) + h * HD;
#pragma unroll
        for (int nt = 0; nt < 8; nt++) {
            uint2 w0 = { f2tf(o0[nt][0] * i00), f2tf(o0[nt][1] * i00) };
            uint2 w1 = { f2tf(o0[nt][2] * i01), f2tf(o0[nt][3] * i01) };
            uint2 w2 = { f2tf(o1[nt][0] * i10), f2tf(o1[nt][1] * i10) };
            uint2 w3 = { f2tf(o1[nt][2] * i11), f2tf(o1[nt][3] * i11) };
            *(uint2*)(b0 + nt * 8 + 2 * fc) = w0;
            *(uint2*)(b1 + nt * 8 + 2 * fc) = w1;
            *(uint2*)(b2 + nt * 8 + 2 * fc) = w2;
            *(uint2*)(b3 + nt * 8 + 2 * fc) = w3;
        }
    }
}

// =====================================================================
// launch
// =====================================================================
extern "C" void kernel_launch(void* const* d_in, const int* in_sizes, int n_in,
                              void* d_out, int out_size)
{
    const float* x  = (const float*)d_in[0];
    const float* Wq = (const float*)d_in[1];
    const float* Wk = (const float*)d_in[2];
    const float* Wv = (const float*)d_in[3];
    const float* Wo = (const float*)d_in[4];
    const float* bo = (const float*)d_in[5];
    float* out = (float*)d_out;

    float *qp, *kp, *vp;
    cudaGetSymbolAddress((void**)&qp, g_q);
    cudaGetSymbolAddress((void**)&kp, g_k);
    cudaGetSymbolAddress((void**)&vp, g_v);

    preround<<<TOT4 / 256, 256>>>(x, Wq, Wk, Wv, Wo);

    cudaFuncSetAttribute(gemm_qkv, cudaFuncAttributeMaxDynamicSharedMemorySize, GSMEM_DYN);
    cudaFuncSetAttribute(gemm_out, cudaFuncAttributeMaxDynamicSharedMemorySize, GSMEM_DYN);

    gemm_qkv<<<dim3(8, MROWS / 128), 256, GSMEM_DYN>>>(qp, kp, vp);

    int smemf = (128 * LTK + 128 * LTV + 128 * LTT) * (int)sizeof(uint32_t);  // 108544
    cudaFuncSetAttribute(flash_mma, cudaFuncAttributeMaxDynamicSharedMemorySize, smemf);
    flash_mma<<<dim3(SEQ / 128, NH, NB), 128, smemf>>>();

    gemm_out<<<dim3(EMB / 256, MROWS / 128), 256, GSMEM_DYN>>>(bo, out);
}

// round 13
// speedup vs baseline: 1.7426x; 1.7426x over previous
#include <cuda_runtime.h>
#include <cuda_fp16.h>
#include <math.h>
#include <stdint.h>

#define NB   2
#define SEQ  2048
#define EMB  1024
#define NH   16
#define NKV  8
#define HD   64
#define MROWS (NB*SEQ)   // 4096

// ---------------- scratch (no allocations allowed) ----------------
__device__ __half g_q [(size_t)MROWS * NH * HD];   // QSC-scaled fp16
__device__ __half g_k [(size_t)MROWS * NKV * HD];  // fp16, [tok][kvh*64+d]
__device__ __half g_vt[(size_t)MROWS * NKV * HD];  // fp16, [nb][kvh][d][s] (transposed)
__device__ __half g_attn[(size_t)MROWS * NH * HD]; // fp16
__device__ __half g_xt[(size_t)MROWS * EMB];       // fp16 x
__device__ __half g_wq[(size_t)NH * HD * EMB];
__device__ __half g_wk[(size_t)NKV * HD * EMB];
__device__ __half g_wv[(size_t)NKV * HD * EMB];
__device__ __half g_wo[(size_t)EMB * NH * HD];

#define QSC 0.18033688011112042f   // 0.125 * log2(e)

// =====================================================================
// helpers
// =====================================================================
__device__ __forceinline__ uint32_t f2h2(float lo, float hi) {
    uint32_t r;
    asm("cvt.rn.f16x2.f32 %0, %1, %2;" : "=r"(r) : "f"(hi), "f"(lo));
    return r;
}
__device__ __forceinline__ void mma_f16(float* d, const uint32_t* a, const uint32_t* b) {
    asm volatile(
        "mma.sync.aligned.m16n8k16.row.col.f32.f16.f16.f32 "
        "{%0,%1,%2,%3}, {%4,%5,%6,%7}, {%8,%9}, {%0,%1,%2,%3};"
        : "+f"(d[0]), "+f"(d[1]), "+f"(d[2]), "+f"(d[3])
        : "r"(a[0]), "r"(a[1]), "r"(a[2]), "r"(a[3]), "r"(b[0]), "r"(b[1]));
}
__device__ __forceinline__ uint32_t smem_u32(const void* p) {
    uint32_t a;
    asm("{ .reg .u64 t; cvta.to.shared.u64 t, %1; cvt.u32.u64 %0, t; }" : "=r"(a) : "l"(p));
    return a;
}
#define CPCA16(dst, src) \
    asm volatile("cp.async.ca.shared.global [%0], [%1], 16;" :: "r"(dst), "l"(src))
#define CP_COMMIT() asm volatile("cp.async.commit_group;" ::: "memory")
#define CP_WAIT(n)  asm volatile("cp.async.wait_group %0;" :: "n"(n) : "memory")

// =====================================================================
// pre-round: x + weights -> fp16 scratch
// =====================================================================
#define X4  (MROWS * EMB / 4)
#define WQ4 (NH * HD * EMB / 4)
#define WK4 (NKV * HD * EMB / 4)
#define TOT4 (X4 + WQ4 + 2 * WK4 + WQ4)

__global__ __launch_bounds__(256)
void preround(const float* __restrict__ x,
              const float* __restrict__ wq, const float* __restrict__ wk,
              const float* __restrict__ wv, const float* __restrict__ wo)
{
    long i = (long)blockIdx.x * 256 + threadIdx.x;
    const float* src; __half* dst; long base;
    if (i < X4)                       { src = x;  dst = g_xt; base = 0; }
    else if (i < X4 + WQ4)            { src = wq; dst = g_wq; base = X4; }
    else if (i < X4 + WQ4 + WK4)      { src = wk; dst = g_wk; base = X4 + WQ4; }
    else if (i < X4 + WQ4 + 2 * WK4)  { src = wv; dst = g_wv; base = X4 + WQ4 + WK4; }
    else                              { src = wo; dst = g_wo; base = X4 + WQ4 + 2 * WK4; }
    long j = (i - base) * 4;
    float4 a = *(const float4*)(src + j);
    uint2 t = { f2h2(a.x, a.y), f2h2(a.z, a.w) };
    *(uint2*)(dst + j) = t;
}

// =====================================================================
// fp16 GEMM: 256 thr, 8 warps (2x4), warp 64x64, CTA 128x256,
// K-chunk 64 halves (4 x k16 steps), cp.async.ca double-buffered.
// C[M,N] = A[M,K] @ B[N,K]^T
// mode 0: fp32 +bias out; mode 1: fp16 out; mode 2: QSC*fp16 out;
// mode 3: V-transpose fp16 out into g_vt[nb][kvh][d][s].
// =====================================================================
#define LT 36                      // words per row (64 halves = 32 w + 4 pad)
#define ABUF (128 * LT)
#define BBUF (256 * LT)
#define TBUF (ABUF + BBUF)         // 13824 words
#define GSMEM_DYN (2 * TBUF * 4)   // 110592 B

__device__ __forceinline__
void gemm_stage(uint32_t sbase, int buf, const __half* __restrict__ A,
                const __half* __restrict__ B, int K, int m0, int n0, int k0, int tid)
{
    uint32_t dA = sbase + (buf * TBUF) * 4;
    uint32_t dB = dA + ABUF * 4;
    // A: 128 rows x 8 chunks(16B = 8 halves) = 1024 -> 4/thread
#pragma unroll
    for (int p = 0; p < 4; p++) {
        int c = tid + p * 256;
        int row = c >> 3;
        int ch  = c & 7;
        CPCA16(dA + (row * LT + ch * 4) * 4, A + (size_t)(m0 + row) * K + k0 + ch * 8);
    }
    // B: 256 rows x 8 = 2048 -> 8/thread
#pragma unroll
    for (int p = 0; p < 8; p++) {
        int c = tid + p * 256;
        int row = c >> 3;
        int ch  = c & 7;
        CPCA16(dB + (row * LT + ch * 4) * 4, B + (size_t)(n0 + row) * K + k0 + ch * 8);
    }
    CP_COMMIT();
}

__device__ __forceinline__
void gemm_body(const __half* __restrict__ A, const __half* __restrict__ B,
               const float* __restrict__ bias, void* __restrict__ Cout,
               int N, int K, int m0, int n0, int mode)
{
    extern __shared__ uint32_t gsm[];
    const uint32_t sbase = smem_u32(gsm);

    const int tid  = threadIdx.x;
    const int lane = tid & 31;
    const int wid  = tid >> 5;
    const int wm   = wid >> 2;
    const int wn   = wid & 3;
    const int fr   = lane >> 2;
    const int fc   = lane & 3;

    float acc[4][8][4];
#pragma unroll
    for (int mt = 0; mt < 4; mt++)
#pragma unroll
        for (int nt = 0; nt < 8; nt++)
#pragma unroll
            for (int i = 0; i < 4; i++) acc[mt][nt][i] = 0.f;

    gemm_stage(sbase, 0, A, B, K, m0, n0, 0, tid);

    const int NC = K / 64;
    for (int ch = 0; ch < NC; ch++) {
        if (ch + 1 < NC) {
            gemm_stage(sbase, (ch + 1) & 1, A, B, K, m0, n0, (ch + 1) * 64, tid);
            CP_WAIT(1);
        } else {
            CP_WAIT(0);
        }
        __syncthreads();

        const uint32_t* As = gsm + (ch & 1) * TBUF;
        const uint32_t* Bs = As + ABUF;

#pragma unroll
        for (int ks = 0; ks < 4; ks++) {      // 4 x k16 steps
            uint32_t af[4][4], bf[8][2];
#pragma unroll
            for (int mt = 0; mt < 4; mt++) {
                int m = wm * 64 + mt * 16 + fr;
                af[mt][0] = As[m * LT + ks * 8 + fc];
                af[mt][1] = As[(m + 8) * LT + ks * 8 + fc];
                af[mt][2] = As[m * LT + ks * 8 + fc + 4];
                af[mt][3] = As[(m + 8) * LT + ks * 8 + fc + 4];
            }
#pragma unroll
            for (int nt = 0; nt < 8; nt++) {
                int n = wn * 64 + nt * 8 + fr;
                bf[nt][0] = Bs[n * LT + ks * 8 + fc];
                bf[nt][1] = Bs[n * LT + ks * 8 + fc + 4];
            }
#pragma unroll
            for (int mt = 0; mt < 4; mt++)
#pragma unroll
                for (int nt = 0; nt < 8; nt++)
                    mma_f16(acc[mt][nt], af[mt], bf[nt]);
        }
        __syncthreads();
    }

    const int c2 = fc * 2;
#pragma unroll
    for (int mt = 0; mt < 4; mt++) {
        int m = m0 + wm * 64 + mt * 16 + fr;
#pragma unroll
        for (int nt = 0; nt < 8; nt++) {
            int n = n0 + wn * 64 + nt * 8 + c2;
            if (mode == 0) {
                float* C = (float*)Cout;
                float b0 = bias ? bias[n] : 0.f, b1 = bias ? bias[n + 1] : 0.f;
                float2 v0 = { acc[mt][nt][0] + b0, acc[mt][nt][1] + b1 };
                float2 v1 = { acc[mt][nt][2] + b0, acc[mt][nt][3] + b1 };
                *(float2*)(C + (size_t)m * N + n)       = v0;
                *(float2*)(C + (size_t)(m + 8) * N + n) = v1;
            } else if (mode == 3) {
                // V transpose: n -> (kvh, d); m -> (nb, s)
                int kvh = n >> 6, d = n & 63;
                int nb = m >> 11, s = m & (SEQ - 1);
                size_t rb = ((size_t)(nb * NKV + kvh) * HD + d) * SEQ;
                g_vt[rb + s]           = __float2half(acc[mt][nt][0]);
                g_vt[rb + SEQ + s]     = __float2half(acc[mt][nt][1]);   // d+1
                g_vt[rb + s + 8]       = __float2half(acc[mt][nt][2]);
                g_vt[rb + SEQ + s + 8] = __float2half(acc[mt][nt][3]);
            } else {
                __half* C = (__half*)Cout;
                float sc = (mode == 2) ? QSC : 1.f;
                *(uint32_t*)(C + (size_t)m * N + n) =
                    f2h2(acc[mt][nt][0] * sc, acc[mt][nt][1] * sc);
                *(uint32_t*)(C + (size_t)(m + 8) * N + n) =
                    f2h2(acc[mt][nt][2] * sc, acc[mt][nt][3] * sc);
            }
        }
    }
}

// fused QKV: bx 0..3 -> Q (mode 2), 4..5 -> K (mode 1), 6..7 -> V (mode 3)
__global__ __launch_bounds__(256)
void gemm_qkv()
{
    const int bx = blockIdx.x;
    const int m0 = blockIdx.y * 128;
    if (bx < 4)      gemm_body(g_xt, g_wq, nullptr, g_q, NH * HD,  EMB, m0, bx * 256, 2);
    else if (bx < 6) gemm_body(g_xt, g_wk, nullptr, g_k, NKV * HD, EMB, m0, (bx - 4) * 256, 1);
    else             gemm_body(g_xt, g_wv, nullptr, nullptr, NKV * HD, EMB, m0, (bx - 6) * 256, 3);
}

__global__ __launch_bounds__(256)
void gemm_out(const float* __restrict__ bias, float* __restrict__ C)
{
    gemm_body(g_attn, g_wo, bias, C, EMB, EMB, blockIdx.y * 128, blockIdx.x * 256, 0);
}

// =====================================================================
// Flash attention, fp16 mma (m16n8k16). 4 warps x 32 q-rows, BQ=128.
// KV staged in 128-key tiles, two 64-key compute passes.
// Ks: [key][d] 64 halves, stride 36 words.  Vt: [d][key] 128 halves,
// stride 68 words.  Ps: [q][*] stride 36 words (Q staging, then P).
// =====================================================================
#define LTK 36
#define LTV 68
#define LTT 36

__global__ __launch_bounds__(128, 2)
void flash_mma()
{
    extern __shared__ uint32_t smf[];
    uint32_t* Ks = smf;                   // [128][36]
    uint32_t* Vt = Ks + 128 * LTK;        // [64][68]
    uint32_t* Ps = Vt + 64 * LTV;         // [128][36]

    const int tid  = threadIdx.x;
    const int lane = tid & 31;
    const int wid  = tid >> 5;
    const int fr   = lane >> 2;
    const int fc   = lane & 3;

    const int q0 = blockIdx.x * 128;
    const int h  = blockIdx.y;
    const int n  = blockIdx.z;
    const int kvh = h >> 1;
    const float slope2 = exp2f(-(float)(h + 1)) * QSC;

    // ---- stage Q (fp16, pre-scaled): 128 rows x 8 chunks -> 8/thread ----
#pragma unroll
    for (int p = 0; p < 8; p++) {
        int u = tid + p * 128;
        int qi = u >> 3;
        int c  = u & 7;
        uint4 t = *(const uint4*)(g_q + (size_t)(n * SEQ + q0 + qi) * (NH * HD)
                                      + h * HD + c * 8);
        *(uint4*)&Ps[qi * LTT + c * 4] = t;
    }
    __syncthreads();

    const int r0 = wid * 32 + fr;
    uint32_t qf0[4][4], qf1[4][4];
#pragma unroll
    for (int ks = 0; ks < 4; ks++) {
        qf0[ks][0] = Ps[r0 * LTT + ks * 8 + fc];
        qf0[ks][1] = Ps[(r0 + 8) * LTT + ks * 8 + fc];
        qf0[ks][2] = Ps[r0 * LTT + ks * 8 + fc + 4];
        qf0[ks][3] = Ps[(r0 + 8) * LTT + ks * 8 + fc + 4];
        qf1[ks][0] = Ps[(r0 + 16) * LTT + ks * 8 + fc];
        qf1[ks][1] = Ps[(r0 + 24) * LTT + ks * 8 + fc];
        qf1[ks][2] = Ps[(r0 + 16) * LTT + ks * 8 + fc + 4];
        qf1[ks][3] = Ps[(r0 + 24) * LTT + ks * 8 + fc + 4];
    }

    float o0[8][4], o1[8][4];
#pragma unroll
    for (int nt = 0; nt < 8; nt++)
#pragma unroll
        for (int i = 0; i < 4; i++) { o0[nt][i] = 0.f; o1[nt][i] = 0.f; }
    float m00 = -INFINITY, m01 = -INFINITY, m10 = -INFINITY, m11 = -INFINITY;
    float l00 = 0.f, l01 = 0.f, l10 = 0.f, l11 = 0.f;

    const float gq0 = (float)(q0 + wid * 32 + fr);

    for (int kb = 0; kb < SEQ / 128; kb++) {
        __syncthreads();

        // ---- stage K [128 keys][64 halves] and Vt [64 d][128 halves] ----
#pragma unroll
        for (int p = 0; p < 8; p++) {
            int u = tid + p * 128;
            int ki = u >> 3;
            int c  = u & 7;
            uint4 t = *(const uint4*)(g_k + (size_t)(n * SEQ + kb * 128 + ki) * (NKV * HD)
                                          + kvh * HD + c * 8);
            *(uint4*)&Ks[ki * LTK + c * 4] = t;
        }
#pragma unroll
        for (int p = 0; p < 8; p++) {
            int u = tid + p * 128;
            int d = u >> 4;
            int c = u & 15;
            uint4 t = *(const uint4*)(g_vt + ((size_t)(n * NKV + kvh) * HD + d) * SEQ
                                           + kb * 128 + c * 8);
            *(uint4*)&Vt[d * LTV + c * 4] = t;
        }
        __syncthreads();

        // ---- two 64-key compute passes ----
#pragma unroll
        for (int kk = 0; kk < 2; kk++) {
            const uint32_t* K_ = Ks + kk * 64 * LTK;

            float s0[8][4], s1[8][4];
#pragma unroll
            for (int nt = 0; nt < 8; nt++)
#pragma unroll
                for (int i = 0; i < 4; i++) { s0[nt][i] = 0.f; s1[nt][i] = 0.f; }

            // S = Q @ K^T : 4 k16 steps
#pragma unroll
            for (int ks = 0; ks < 4; ks++) {
                uint32_t bf[8][2];
#pragma unroll
                for (int nt = 0; nt < 8; nt++) {
                    bf[nt][0] = K_[(nt * 8 + fr) * LTK + ks * 8 + fc];
                    bf[nt][1] = K_[(nt * 8 + fr) * LTK + ks * 8 + fc + 4];
                }
#pragma unroll
                for (int nt = 0; nt < 8; nt++) {
                    mma_f16(s0[nt], qf0[ks], bf[nt]);
                    mma_f16(s1[nt], qf1[ks], bf[nt]);
                }
            }

            // ALiBi (exp2 domain)
#pragma unroll
            for (int nt = 0; nt < 8; nt++) {
                float k0f = (float)(kb * 128 + kk * 64 + nt * 8 + 2 * fc);
                float k1f = k0f + 1.f;
                s0[nt][0] = fmaf(-slope2, fabsf(gq0 - k0f), s0[nt][0]);
                s0[nt][1] = fmaf(-slope2, fabsf(gq0 - k1f), s0[nt][1]);
                s0[nt][2] = fmaf(-slope2, fabsf((gq0 + 8.f) - k0f), s0[nt][2]);
                s0[nt][3] = fmaf(-slope2, fabsf((gq0 + 8.f) - k1f), s0[nt][3]);
                s1[nt][0] = fmaf(-slope2, fabsf((gq0 + 16.f) - k0f), s1[nt][0]);
                s1[nt][1] = fmaf(-slope2, fabsf((gq0 + 16.f) - k1f), s1[nt][1]);
                s1[nt][2] = fmaf(-slope2, fabsf((gq0 + 24.f) - k0f), s1[nt][2]);
                s1[nt][3] = fmaf(-slope2, fabsf((gq0 + 24.f) - k1f), s1[nt][3]);
            }

            // online softmax, block0 (rows fr, fr+8)
            {
                float mt0 = -INFINITY, mt1 = -INFINITY;
#pragma unroll
                for (int nt = 0; nt < 8; nt++) {
                    mt0 = fmaxf(mt0, fmaxf(s0[nt][0], s0[nt][1]));
                    mt1 = fmaxf(mt1, fmaxf(s0[nt][2], s0[nt][3]));
                }
                mt0 = fmaxf(mt0, __shfl_xor_sync(0xffffffffu, mt0, 1));
                mt0 = fmaxf(mt0, __shfl_xor_sync(0xffffffffu, mt0, 2));
                mt1 = fmaxf(mt1, __shfl_xor_sync(0xffffffffu, mt1, 1));
                mt1 = fmaxf(mt1, __shfl_xor_sync(0xffffffffu, mt1, 2));
                float mn0 = fmaxf(m00, mt0), mn1 = fmaxf(m01, mt1);
                float c0 = exp2f(m00 - mn0), c1 = exp2f(m01 - mn1);
                m00 = mn0; m01 = mn1;
                float rs0 = 0.f, rs1 = 0.f;
#pragma unroll
                for (int nt = 0; nt < 8; nt++) {
                    float p0 = exp2f(s0[nt][0] - mn0);
                    float p1 = exp2f(s0[nt][1] - mn0);
                    float p2 = exp2f(s0[nt][2] - mn1);
                    float p3 = exp2f(s0[nt][3] - mn1);
                    rs0 += p0 + p1; rs1 += p2 + p3;
                    Ps[r0 * LTT + nt * 4 + fc]       = f2h2(p0, p1);
                    Ps[(r0 + 8) * LTT + nt * 4 + fc] = f2h2(p2, p3);
                }
                rs0 += __shfl_xor_sync(0xffffffffu, rs0, 1);
                rs0 += __shfl_xor_sync(0xffffffffu, rs0, 2);
                rs1 += __shfl_xor_sync(0xffffffffu, rs1, 1);
                rs1 += __shfl_xor_sync(0xffffffffu, rs1, 2);
                l00 = l00 * c0 + rs0;
                l01 = l01 * c1 + rs1;
#pragma unroll
                for (int nt = 0; nt < 8; nt++) {
                    o0[nt][0] *= c0; o0[nt][1] *= c0;
                    o0[nt][2] *= c1; o0[nt][3] *= c1;
                }
            }
            // online softmax, block1 (rows fr+16, fr+24)
            {
                float mt0 = -INFINITY, mt1 = -INFINITY;
#pragma unroll
                for (int nt = 0; nt < 8; nt++) {
                    mt0 = fmaxf(mt0, fmaxf(s1[nt][0], s1[nt][1]));
                    mt1 = fmaxf(mt1, fmaxf(s1[nt][2], s1[nt][3]));
                }
                mt0 = fmaxf(mt0, __shfl_xor_sync(0xffffffffu, mt0, 1));
                mt0 = fmaxf(mt0, __shfl_xor_sync(0xffffffffu, mt0, 2));
                mt1 = fmaxf(mt1, __shfl_xor_sync(0xffffffffu, mt1, 1));
                mt1 = fmaxf(mt1, __shfl_xor_sync(0xffffffffu, mt1, 2));
                float mn0 = fmaxf(m10, mt0), mn1 = fmaxf(m11, mt1);
                float c0 = exp2f(m10 - mn0), c1 = exp2f(m11 - mn1);
                m10 = mn0; m11 = mn1;
                float rs0 = 0.f, rs1 = 0.f;
#pragma unroll
                for (int nt = 0; nt < 8; nt++) {
                    float p0 = exp2f(s1[nt][0] - mn0);
                    float p1 = exp2f(s1[nt][1] - mn0);
                    float p2 = exp2f(s1[nt][2] - mn1);
                    float p3 = exp2f(s1[nt][3] - mn1);
                    rs0 += p0 + p1; rs1 += p2 + p3;
                    Ps[(r0 + 16) * LTT + nt * 4 + fc] = f2h2(p0, p1);
                    Ps[(r0 + 24) * LTT + nt * 4 + fc] = f2h2(p2, p3);
                }
                rs0 += __shfl_xor_sync(0xffffffffu, rs0, 1);
                rs0 += __shfl_xor_sync(0xffffffffu, rs0, 2);
                rs1 += __shfl_xor_sync(0xffffffffu, rs1, 1);
                rs1 += __shfl_xor_sync(0xffffffffu, rs1, 2);
                l10 = l10 * c0 + rs0;
                l11 = l11 * c1 + rs1;
#pragma unroll
                for (int nt = 0; nt < 8; nt++) {
                    o1[nt][0] *= c0; o1[nt][1] *= c0;
                    o1[nt][2] *= c1; o1[nt][3] *= c1;
                }
            }
            __syncwarp();

            // O += P @ V : 4 k16 steps over the 64 keys
#pragma unroll
            for (int ks = 0; ks < 4; ks++) {
                uint32_t af0[4], af1[4], bf[8][2];
                af0[0] = Ps[r0 * LTT + ks * 8 + fc];
                af0[1] = Ps[(r0 + 8) * LTT + ks * 8 + fc];
                af0[2] = Ps[r0 * LTT + ks * 8 + fc + 4];
                af0[3] = Ps[(r0 + 8) * LTT + ks * 8 + fc + 4];
                af1[0] = Ps[(r0 + 16) * LTT + ks * 8 + fc];
                af1[1] = Ps[(r0 + 24) * LTT + ks * 8 + fc];
                af1[2] = Ps[(r0 + 16) * LTT + ks * 8 + fc + 4];
                af1[3] = Ps[(r0 + 24) * LTT + ks * 8 + fc + 4];
#pragma unroll
                for (int nt = 0; nt < 8; nt++) {
                    bf[nt][0] = Vt[(nt * 8 + fr) * LTV + kk * 32 + ks * 8 + fc];
                    bf[nt][1] = Vt[(nt * 8 + fr) * LTV + kk * 32 + ks * 8 + fc + 4];
                }
#pragma unroll
                for (int nt = 0; nt < 8; nt++) {
                    mma_f16(o0[nt], af0, bf[nt]);
                    mma_f16(o1[nt], af1, bf[nt]);
                }
            }
            __syncwarp();   // Ps reuse between passes
        }
    }

    // ---- normalize + write fp16 ----
    {
        float i00 = 1.f / l00, i01 = 1.f / l01, i10 = 1.f / l10, i11 = 1.f / l11;
        const int qr = q0 + wid * 32 + fr;
        __half* b0 = g_attn + (size_t)(n * SEQ + qr) * (NH * HD) + h * HD;
        __half* b1 = g_attn + (size_t)(n * SEQ + qr + 8) * (NH * HD) + h * HD;
        __half* b2 = g_attn + (size_t)(n * SEQ + qr + 16) * (NH * HD) + h * HD;
        __half* b3 = g_attn + (size_t)(n * SEQ + qr + 24) * (NH * HD) + h * HD;
#pragma unroll
        for (int nt = 0; nt < 8; nt++) {
            *(uint32_t*)(b0 + nt * 8 + 2 * fc) = f2h2(o0[nt][0] * i00, o0[nt][1] * i00);
            *(uint32_t*)(b1 + nt * 8 + 2 * fc) = f2h2(o0[nt][2] * i01, o0[nt][3] * i01);
            *(uint32_t*)(b2 + nt * 8 + 2 * fc) = f2h2(o1[nt][0] * i10, o1[nt][1] * i10);
            *(uint32_t*)(b3 + nt * 8 + 2 * fc) = f2h2(o1[nt][2] * i11, o1[nt][3] * i11);
        }
    }
}

// =====================================================================
// launch
// =====================================================================
extern "C" void kernel_launch(void* const* d_in, const int* in_sizes, int n_in,
                              void* d_out, int out_size)
{
    const float* x  = (const float*)d_in[0];
    const float* Wq = (const float*)d_in[1];
    const float* Wk = (const float*)d_in[2];
    const float* Wv = (const float*)d_in[3];
    const float* Wo = (const float*)d_in[4];
    const float* bo = (const float*)d_in[5];
    float* out = (float*)d_out;

    preround<<<TOT4 / 256, 256>>>(x, Wq, Wk, Wv, Wo);

    cudaFuncSetAttribute(gemm_qkv, cudaFuncAttributeMaxDynamicSharedMemorySize, GSMEM_DYN);
    cudaFuncSetAttribute(gemm_out, cudaFuncAttributeMaxDynamicSharedMemorySize, GSMEM_DYN);

    gemm_qkv<<<dim3(8, MROWS / 128), 256, GSMEM_DYN>>>();

    int smemf = (128 * LTK + 64 * LTV + 128 * LTT) * (int)sizeof(uint32_t);  // 54272
    cudaFuncSetAttribute(flash_mma, cudaFuncAttributeMaxDynamicSharedMemorySize, smemf);
    flash_mma<<<dim3(SEQ / 128, NH, NB), 128, smemf>>>();

    gemm_out<<<dim3(EMB / 256, MROWS / 128), 256, GSMEM_DYN>>>(bo, out);
}

// round 14
// speedup vs baseline: 1.8679x; 1.0719x over previous
#include <cuda_runtime.h>
#include <cuda_fp16.h>
#include <math.h>
#include <stdint.h>

#define NB   2
#define SEQ  2048
#define EMB  1024
#define NH   16
#define NKV  8
#define HD   64
#define MROWS (NB*SEQ)   // 4096

// ---------------- scratch (no allocations allowed) ----------------
__device__ __half g_q [(size_t)MROWS * NH * HD];   // QSC-scaled fp16
__device__ __half g_k [(size_t)MROWS * NKV * HD];  // fp16
__device__ __half g_vt[(size_t)MROWS * NKV * HD];  // fp16 transposed [nb][kvh][d][s]
__device__ __half g_attn[(size_t)MROWS * NH * HD];
__device__ __half g_xt[(size_t)MROWS * EMB];
__device__ __half g_wq[(size_t)NH * HD * EMB];
__device__ __half g_wk[(size_t)NKV * HD * EMB];
__device__ __half g_wv[(size_t)NKV * HD * EMB];
__device__ __half g_wo[(size_t)EMB * NH * HD];

#define QSC 0.18033688011112042f   // 0.125 * log2(e)

// =====================================================================
// helpers
// =====================================================================
__device__ __forceinline__ uint32_t f2h2(float lo, float hi) {
    uint32_t r;
    asm("cvt.rn.f16x2.f32 %0, %1, %2;" : "=r"(r) : "f"(hi), "f"(lo));
    return r;
}
__device__ __forceinline__ void mma_f16(float* d, const uint32_t* a, const uint32_t* b) {
    asm volatile(
        "mma.sync.aligned.m16n8k16.row.col.f32.f16.f16.f32 "
        "{%0,%1,%2,%3}, {%4,%5,%6,%7}, {%8,%9}, {%0,%1,%2,%3};"
        : "+f"(d[0]), "+f"(d[1]), "+f"(d[2]), "+f"(d[3])
        : "r"(a[0]), "r"(a[1]), "r"(a[2]), "r"(a[3]), "r"(b[0]), "r"(b[1]));
}
__device__ __forceinline__ void ldsm_x4(uint32_t* r, uint32_t addr) {
    asm volatile("ldmatrix.sync.aligned.m8n8.x4.shared.b16 {%0,%1,%2,%3}, [%4];"
        : "=r"(r[0]), "=r"(r[1]), "=r"(r[2]), "=r"(r[3]) : "r"(addr));
}
__device__ __forceinline__ uint32_t smem_u32(const void* p) {
    uint32_t a;
    asm("{ .reg .u64 t; cvta.to.shared.u64 t, %1; cvt.u32.u64 %0, t; }" : "=r"(a) : "l"(p));
    return a;
}
#define CPCA16(dst, src) \
    asm volatile("cp.async.ca.shared.global [%0], [%1], 16;" :: "r"(dst), "l"(src))
#define CP_COMMIT() asm volatile("cp.async.commit_group;" ::: "memory")
#define CP_WAIT(n)  asm volatile("cp.async.wait_group %0;" :: "n"(n) : "memory")

// =====================================================================
// pre-round: x + weights -> fp16 scratch
// =====================================================================
#define X4  (MROWS * EMB / 4)
#define WQ4 (NH * HD * EMB / 4)
#define WK4 (NKV * HD * EMB / 4)
#define TOT4 (X4 + WQ4 + 2 * WK4 + WQ4)

__global__ __launch_bounds__(256)
void preround(const float* __restrict__ x,
              const float* __restrict__ wq, const float* __restrict__ wk,
              const float* __restrict__ wv, const float* __restrict__ wo)
{
    long i = (long)blockIdx.x * 256 + threadIdx.x;
    const float* src; __half* dst; long base;
    if (i < X4)                       { src = x;  dst = g_xt; base = 0; }
    else if (i < X4 + WQ4)            { src = wq; dst = g_wq; base = X4; }
    else if (i < X4 + WQ4 + WK4)      { src = wk; dst = g_wk; base = X4 + WQ4; }
    else if (i < X4 + WQ4 + 2 * WK4)  { src = wv; dst = g_wv; base = X4 + WQ4 + WK4; }
    else                              { src = wo; dst = g_wo; base = X4 + WQ4 + 2 * WK4; }
    long j = (i - base) * 4;
    float4 a = *(const float4*)(src + j);
    uint2 t = { f2h2(a.x, a.y), f2h2(a.z, a.w) };
    *(uint2*)(dst + j) = t;
}

// =====================================================================
// fp16 GEMM (ldmatrix fragments): 256 thr, 8 warps (2x4), warp 64x64,
// CTA 128x256, K-chunk 64 halves, cp.async.ca double-buffered.
// =====================================================================
#define LT 36
#define ABUF (128 * LT)
#define BBUF (256 * LT)
#define TBUF (ABUF + BBUF)
#define GSMEM_DYN (2 * TBUF * 4)

__device__ __forceinline__
void gemm_stage(uint32_t sbase, int buf, const __half* __restrict__ A,
                const __half* __restrict__ B, int K, int m0, int n0, int k0, int tid)
{
    uint32_t dA = sbase + (buf * TBUF) * 4;
    uint32_t dB = dA + ABUF * 4;
#pragma unroll
    for (int p = 0; p < 4; p++) {
        int c = tid + p * 256;
        int row = c >> 3;
        int ch  = c & 7;
        CPCA16(dA + (row * LT + ch * 4) * 4, A + (size_t)(m0 + row) * K + k0 + ch * 8);
    }
#pragma unroll
    for (int p = 0; p < 8; p++) {
        int c = tid + p * 256;
        int row = c >> 3;
        int ch  = c & 7;
        CPCA16(dB + (row * LT + ch * 4) * 4, B + (size_t)(n0 + row) * K + k0 + ch * 8);
    }
    CP_COMMIT();
}

__device__ __forceinline__
void gemm_body(const __half* __restrict__ A, const __half* __restrict__ B,
               const float* __restrict__ bias, void* __restrict__ Cout,
               int N, int K, int m0, int n0, int mode)
{
    extern __shared__ uint32_t gsm[];
    const uint32_t sbase = smem_u32(gsm);

    const int tid  = threadIdx.x;
    const int lane = tid & 31;
    const int wid  = tid >> 5;
    const int wm   = wid >> 2;
    const int wn   = wid & 3;
    const int fr   = lane >> 2;
    const int fc   = lane & 3;

    // ldmatrix lane address components
    const int rowA = (lane & 7) + ((lane >> 3) & 1) * 8;   // A-operand pattern
    const int offA = (lane >> 4) * 4;
    const int rowB = (lane & 7) + (lane >> 4) * 8;         // B-operand pattern
    const int offB = ((lane >> 3) & 1) * 4;

    float acc[4][8][4];
#pragma unroll
    for (int mt = 0; mt < 4; mt++)
#pragma unroll
        for (int nt = 0; nt < 8; nt++)
#pragma unroll
            for (int i = 0; i < 4; i++) acc[mt][nt][i] = 0.f;

    gemm_stage(sbase, 0, A, B, K, m0, n0, 0, tid);

    const int NC = K / 64;
    for (int ch = 0; ch < NC; ch++) {
        if (ch + 1 < NC) {
            gemm_stage(sbase, (ch + 1) & 1, A, B, K, m0, n0, (ch + 1) * 64, tid);
            CP_WAIT(1);
        } else {
            CP_WAIT(0);
        }
        __syncthreads();

        const uint32_t asu = sbase + ((ch & 1) * TBUF) * 4;
        const uint32_t bsu = asu + ABUF * 4;

#pragma unroll
        for (int ks = 0; ks < 4; ks++) {
            uint32_t af[4][4], bf[8][2];
#pragma unroll
            for (int mt = 0; mt < 4; mt++)
                ldsm_x4(af[mt], asu + (((wm * 64 + mt * 16 + rowA) * LT) + ks * 8 + offA) * 4);
#pragma unroll
            for (int ntp = 0; ntp < 4; ntp++) {
                uint32_t m[4];
                ldsm_x4(m, bsu + (((wn * 64 + ntp * 16 + rowB) * LT) + ks * 8 + offB) * 4);
                bf[ntp * 2][0] = m[0]; bf[ntp * 2][1] = m[1];
                bf[ntp * 2 + 1][0] = m[2]; bf[ntp * 2 + 1][1] = m[3];
            }
#pragma unroll
            for (int mt = 0; mt < 4; mt++)
#pragma unroll
                for (int nt = 0; nt < 8; nt++)
                    mma_f16(acc[mt][nt], af[mt], bf[nt]);
        }
        __syncthreads();
    }

    const int c2 = fc * 2;
#pragma unroll
    for (int mt = 0; mt < 4; mt++) {
        int m = m0 + wm * 64 + mt * 16 + fr;
#pragma unroll
        for (int nt = 0; nt < 8; nt++) {
            int n = n0 + wn * 64 + nt * 8 + c2;
            if (mode == 0) {
                float* C = (float*)Cout;
                float b0 = bias ? bias[n] : 0.f, b1 = bias ? bias[n + 1] : 0.f;
                float2 v0 = { acc[mt][nt][0] + b0, acc[mt][nt][1] + b1 };
                float2 v1 = { acc[mt][nt][2] + b0, acc[mt][nt][3] + b1 };
                *(float2*)(C + (size_t)m * N + n)       = v0;
                *(float2*)(C + (size_t)(m + 8) * N + n) = v1;
            } else if (mode == 3) {
                int kvh = n >> 6, d = n & 63;
                int nb = m >> 11, s = m & (SEQ - 1);
                size_t rb = ((size_t)(nb * NKV + kvh) * HD + d) * SEQ;
                g_vt[rb + s]           = __float2half(acc[mt][nt][0]);
                g_vt[rb + SEQ + s]     = __float2half(acc[mt][nt][1]);
                g_vt[rb + s + 8]       = __float2half(acc[mt][nt][2]);
                g_vt[rb + SEQ + s + 8] = __float2half(acc[mt][nt][3]);
            } else {
                __half* C = (__half*)Cout;
                float sc = (mode == 2) ? QSC : 1.f;
                *(uint32_t*)(C + (size_t)m * N + n) =
                    f2h2(acc[mt][nt][0] * sc, acc[mt][nt][1] * sc);
                *(uint32_t*)(C + (size_t)(m + 8) * N + n) =
                    f2h2(acc[mt][nt][2] * sc, acc[mt][nt][3] * sc);
            }
        }
    }
}

__global__ __launch_bounds__(256)
void gemm_qkv()
{
    const int bx = blockIdx.x;
    const int m0 = blockIdx.y * 128;
    if (bx < 4)      gemm_body(g_xt, g_wq, nullptr, g_q, NH * HD,  EMB, m0, bx * 256, 2);
    else if (bx < 6) gemm_body(g_xt, g_wk, nullptr, g_k, NKV * HD, EMB, m0, (bx - 4) * 256, 1);
    else             gemm_body(g_xt, g_wv, nullptr, nullptr, NKV * HD, EMB, m0, (bx - 6) * 256, 3);
}

__global__ __launch_bounds__(256)
void gemm_out(const float* __restrict__ bias, float* __restrict__ C)
{
    gemm_body(g_attn, g_wo, bias, C, EMB, EMB, blockIdx.y * 128, blockIdx.x * 256, 0);
}

// =====================================================================
// Flash attention, fp16 mma + ldmatrix fragments.
// 4 warps x 32 q-rows, BQ=128, 128-key staged tiles, 2 passes.
// Ks: [key][d] stride 36 w.  Vt: [d][key] stride 68 w.  Ps: [q][*] 36 w.
// =====================================================================
#define LTK 36
#define LTV 68
#define LTT 36

__global__ __launch_bounds__(128, 2)
void flash_mma()
{
    extern __shared__ uint32_t smf[];
    uint32_t* Ks = smf;                   // [128][36]
    uint32_t* Vt = Ks + 128 * LTK;        // [64][68]
    uint32_t* Ps = Vt + 64 * LTV;         // [128][36]
    const uint32_t ksu = smem_u32(Ks);
    const uint32_t vtu = smem_u32(Vt);
    const uint32_t psu = smem_u32(Ps);

    const int tid  = threadIdx.x;
    const int lane = tid & 31;
    const int wid  = tid >> 5;
    const int fr   = lane >> 2;
    const int fc   = lane & 3;

    const int rowA = (lane & 7) + ((lane >> 3) & 1) * 8;
    const int offA = (lane >> 4) * 4;
    const int rowB = (lane & 7) + (lane >> 4) * 8;
    const int offB = ((lane >> 3) & 1) * 4;

    const int q0 = blockIdx.x * 128;
    const int h  = blockIdx.y;
    const int n  = blockIdx.z;
    const int kvh = h >> 1;
    const float slope2 = exp2f(-(float)(h + 1)) * QSC;

    // ---- stage Q ----
#pragma unroll
    for (int p = 0; p < 8; p++) {
        int u = tid + p * 128;
        int qi = u >> 3;
        int c  = u & 7;
        uint4 t = *(const uint4*)(g_q + (size_t)(n * SEQ + q0 + qi) * (NH * HD)
                                      + h * HD + c * 8);
        *(uint4*)&Ps[qi * LTT + c * 4] = t;
    }
    __syncthreads();

    const int r0 = wid * 32 + fr;
    uint32_t qf0[4][4], qf1[4][4];
#pragma unroll
    for (int ks = 0; ks < 4; ks++) {
        ldsm_x4(qf0[ks], psu + (((wid * 32 + rowA) * LTT) + ks * 8 + offA) * 4);
        ldsm_x4(qf1[ks], psu + (((wid * 32 + 16 + rowA) * LTT) + ks * 8 + offA) * 4);
    }

    float o0[8][4], o1[8][4];
#pragma unroll
    for (int nt = 0; nt < 8; nt++)
#pragma unroll
        for (int i = 0; i < 4; i++) { o0[nt][i] = 0.f; o1[nt][i] = 0.f; }
    float m00 = -INFINITY, m01 = -INFINITY, m10 = -INFINITY, m11 = -INFINITY;
    float l00 = 0.f, l01 = 0.f, l10 = 0.f, l11 = 0.f;

    const float gq0 = (float)(q0 + wid * 32 + fr);

    for (int kb = 0; kb < SEQ / 128; kb++) {
        __syncthreads();

        // ---- stage K [128][64h] and Vt [64][128h] ----
#pragma unroll
        for (int p = 0; p < 8; p++) {
            int u = tid + p * 128;
            int ki = u >> 3;
            int c  = u & 7;
            uint4 t = *(const uint4*)(g_k + (size_t)(n * SEQ + kb * 128 + ki) * (NKV * HD)
                                          + kvh * HD + c * 8);
            *(uint4*)&Ks[ki * LTK + c * 4] = t;
        }
#pragma unroll
        for (int p = 0; p < 8; p++) {
            int u = tid + p * 128;
            int d = u >> 4;
            int c = u & 15;
            uint4 t = *(const uint4*)(g_vt + ((size_t)(n * NKV + kvh) * HD + d) * SEQ
                                           + kb * 128 + c * 8);
            *(uint4*)&Vt[d * LTV + c * 4] = t;
        }
        __syncthreads();

#pragma unroll
        for (int kk = 0; kk < 2; kk++) {
            float s0[8][4], s1[8][4];
#pragma unroll
            for (int nt = 0; nt < 8; nt++)
#pragma unroll
                for (int i = 0; i < 4; i++) { s0[nt][i] = 0.f; s1[nt][i] = 0.f; }

            // S = Q @ K^T
#pragma unroll
            for (int ks = 0; ks < 4; ks++) {
                uint32_t bf[8][2];
#pragma unroll
                for (int ntp = 0; ntp < 4; ntp++) {
                    uint32_t m[4];
                    ldsm_x4(m, ksu + (((kk * 64 + ntp * 16 + rowB) * LTK) + ks * 8 + offB) * 4);
                    bf[ntp * 2][0] = m[0]; bf[ntp * 2][1] = m[1];
                    bf[ntp * 2 + 1][0] = m[2]; bf[ntp * 2 + 1][1] = m[3];
                }
#pragma unroll
                for (int nt = 0; nt < 8; nt++) {
                    mma_f16(s0[nt], qf0[ks], bf[nt]);
                    mma_f16(s1[nt], qf1[ks], bf[nt]);
                }
            }

            // ALiBi (exp2 domain)
#pragma unroll
            for (int nt = 0; nt < 8; nt++) {
                float k0f = (float)(kb * 128 + kk * 64 + nt * 8 + 2 * fc);
                float k1f = k0f + 1.f;
                s0[nt][0] = fmaf(-slope2, fabsf(gq0 - k0f), s0[nt][0]);
                s0[nt][1] = fmaf(-slope2, fabsf(gq0 - k1f), s0[nt][1]);
                s0[nt][2] = fmaf(-slope2, fabsf((gq0 + 8.f) - k0f), s0[nt][2]);
                s0[nt][3] = fmaf(-slope2, fabsf((gq0 + 8.f) - k1f), s0[nt][3]);
                s1[nt][0] = fmaf(-slope2, fabsf((gq0 + 16.f) - k0f), s1[nt][0]);
                s1[nt][1] = fmaf(-slope2, fabsf((gq0 + 16.f) - k1f), s1[nt][1]);
                s1[nt][2] = fmaf(-slope2, fabsf((gq0 + 24.f) - k0f), s1[nt][2]);
                s1[nt][3] = fmaf(-slope2, fabsf((gq0 + 24.f) - k1f), s1[nt][3]);
            }

            // online softmax, block0
            {
                float mt0 = -INFINITY, mt1 = -INFINITY;
#pragma unroll
                for (int nt = 0; nt < 8; nt++) {
                    mt0 = fmaxf(mt0, fmaxf(s0[nt][0], s0[nt][1]));
                    mt1 = fmaxf(mt1, fmaxf(s0[nt][2], s0[nt][3]));
                }
                mt0 = fmaxf(mt0, __shfl_xor_sync(0xffffffffu, mt0, 1));
                mt0 = fmaxf(mt0, __shfl_xor_sync(0xffffffffu, mt0, 2));
                mt1 = fmaxf(mt1, __shfl_xor_sync(0xffffffffu, mt1, 1));
                mt1 = fmaxf(mt1, __shfl_xor_sync(0xffffffffu, mt1, 2));
                float mn0 = fmaxf(m00, mt0), mn1 = fmaxf(m01, mt1);
                float c0 = exp2f(m00 - mn0), c1 = exp2f(m01 - mn1);
                m00 = mn0; m01 = mn1;
                float rs0 = 0.f, rs1 = 0.f;
#pragma unroll
                for (int nt = 0; nt < 8; nt++) {
                    float p0 = exp2f(s0[nt][0] - mn0);
                    float p1 = exp2f(s0[nt][1] - mn0);
                    float p2 = exp2f(s0[nt][2] - mn1);
                    float p3 = exp2f(s0[nt][3] - mn1);
                    rs0 += p0 + p1; rs1 += p2 + p3;
                    Ps[r0 * LTT + nt * 4 + fc]       = f2h2(p0, p1);
                    Ps[(r0 + 8) * LTT + nt * 4 + fc] = f2h2(p2, p3);
                }
                rs0 += __shfl_xor_sync(0xffffffffu, rs0, 1);
                rs0 += __shfl_xor_sync(0xffffffffu, rs0, 2);
                rs1 += __shfl_xor_sync(0xffffffffu, rs1, 1);
                rs1 += __shfl_xor_sync(0xffffffffu, rs1, 2);
                l00 = l00 * c0 + rs0;
                l01 = l01 * c1 + rs1;
#pragma unroll
                for (int nt = 0; nt < 8; nt++) {
                    o0[nt][0] *= c0; o0[nt][1] *= c0;
                    o0[nt][2] *= c1; o0[nt][3] *= c1;
                }
            }
            // online softmax, block1
            {
                float mt0 = -INFINITY, mt1 = -INFINITY;
#pragma unroll
                for (int nt = 0; nt < 8; nt++) {
                    mt0 = fmaxf(mt0, fmaxf(s1[nt][0], s1[nt][1]));
                    mt1 = fmaxf(mt1, fmaxf(s1[nt][2], s1[nt][3]));
                }
                mt0 = fmaxf(mt0, __shfl_xor_sync(0xffffffffu, mt0, 1));
                mt0 = fmaxf(mt0, __shfl_xor_sync(0xffffffffu, mt0, 2));
                mt1 = fmaxf(mt1, __shfl_xor_sync(0xffffffffu, mt1, 1));
                mt1 = fmaxf(mt1, __shfl_xor_sync(0xffffffffu, mt1, 2));
                float mn0 = fmaxf(m10, mt0), mn1 = fmaxf(m11, mt1);
                float c0 = exp2f(m10 - mn0), c1 = exp2f(m11 - mn1);
                m10 = mn0; m11 = mn1;
                float rs0 = 0.f, rs1 = 0.f;
#pragma unroll
                for (int nt = 0; nt < 8; nt++) {
                    float p0 = exp2f(s1[nt][0] - mn0);
                    float p1 = exp2f(s1[nt][1] - mn0);
                    float p2 = exp2f(s1[nt][2] - mn1);
                    float p3 = exp2f(s1[nt][3] - mn1);
                    rs0 += p0 + p1; rs1 += p2 + p3;
                    Ps[(r0 + 16) * LTT + nt * 4 + fc] = f2h2(p0, p1);
                    Ps[(r0 + 24) * LTT + nt * 4 + fc] = f2h2(p2, p3);
                }
                rs0 += __shfl_xor_sync(0xffffffffu, rs0, 1);
                rs0 += __shfl_xor_sync(0xffffffffu, rs0, 2);
                rs1 += __shfl_xor_sync(0xffffffffu, rs1, 1);
                rs1 += __shfl_xor_sync(0xffffffffu, rs1, 2);
                l10 = l10 * c0 + rs0;
                l11 = l11 * c1 + rs1;
#pragma unroll
                for (int nt = 0; nt < 8; nt++) {
                    o1[nt][0] *= c0; o1[nt][1] *= c0;
                    o1[nt][2] *= c1; o1[nt][3] *= c1;
                }
            }
            __syncwarp();

            // O += P @ V
#pragma unroll
            for (int ks = 0; ks < 4; ks++) {
                uint32_t af0[4], af1[4], bf[8][2];
                ldsm_x4(af0, psu + (((wid * 32 + rowA) * LTT) + ks * 8 + offA) * 4);
                ldsm_x4(af1, psu + (((wid * 32 + 16 + rowA) * LTT) + ks * 8 + offA) * 4);
#pragma unroll
                for (int ntp = 0; ntp < 4; ntp++) {
                    uint32_t m[4];
                    ldsm_x4(m, vtu + (((ntp * 16 + rowB) * LTV) + kk * 32 + ks * 8 + offB) * 4);
                    bf[ntp * 2][0] = m[0]; bf[ntp * 2][1] = m[1];
                    bf[ntp * 2 + 1][0] = m[2]; bf[ntp * 2 + 1][1] = m[3];
                }
#pragma unroll
                for (int nt = 0; nt < 8; nt++) {
                    mma_f16(o0[nt], af0, bf[nt]);
                    mma_f16(o1[nt], af1, bf[nt]);
                }
            }
            __syncwarp();
        }
    }

    // ---- normalize + write fp16 ----
    {
        float i00 = 1.f / l00, i01 = 1.f / l01, i10 = 1.f / l10, i11 = 1.f / l11;
        const int qr = q0 + wid * 32 + fr;
        __half* b0 = g_attn + (size_t)(n * SEQ + qr) * (NH * HD) + h * HD;
        __half* b1 = g_attn + (size_t)(n * SEQ + qr + 8) * (NH * HD) + h * HD;
        __half* b2 = g_attn + (size_t)(n * SEQ + qr + 16) * (NH * HD) + h * HD;
        __half* b3 = g_attn + (size_t)(n * SEQ + qr + 24) * (NH * HD) + h * HD;
#pragma unroll
        for (int nt = 0; nt < 8; nt++) {
            *(uint32_t*)(b0 + nt * 8 + 2 * fc) = f2h2(o0[nt][0] * i00, o0[nt][1] * i00);
            *(uint32_t*)(b1 + nt * 8 + 2 * fc) = f2h2(o0[nt][2] * i01, o0[nt][3] * i01);
            *(uint32_t*)(b2 + nt * 8 + 2 * fc) = f2h2(o1[nt][0] * i10, o1[nt][1] * i10);
            *(uint32_t*)(b3 + nt * 8 + 2 * fc) = f2h2(o1[nt][2] * i11, o1[nt][3] * i11);
        }
    }
}

// =====================================================================
// launch
// =====================================================================
extern "C" void kernel_launch(void* const* d_in, const int* in_sizes, int n_in,
                              void* d_out, int out_size)
{
    const float* x  = (const float*)d_in[0];
    const float* Wq = (const float*)d_in[1];
    const float* Wk = (const float*)d_in[2];
    const float* Wv = (const float*)d_in[3];
    const float* Wo = (const float*)d_in[4];
    const float* bo = (const float*)d_in[5];
    float* out = (float*)d_out;

    preround<<<TOT4 / 256, 256>>>(x, Wq, Wk, Wv, Wo);

    cudaFuncSetAttribute(gemm_qkv, cudaFuncAttributeMaxDynamicSharedMemorySize, GSMEM_DYN);
    cudaFuncSetAttribute(gemm_out, cudaFuncAttributeMaxDynamicSharedMemorySize, GSMEM_DYN);

    gemm_qkv<<<dim3(8, MROWS / 128), 256, GSMEM_DYN>>>();

    int smemf = (128 * LTK + 64 * LTV + 128 * LTT) * (int)sizeof(uint32_t);  // 54272
    cudaFuncSetAttribute(flash_mma, cudaFuncAttributeMaxDynamicSharedMemorySize, smemf);
    flash_mma<<<dim3(SEQ / 128, NH, NB), 128, smemf>>>();

    gemm_out<<<dim3(EMB / 256, MROWS / 128), 256, GSMEM_DYN>>>(bo, out);
}